// round 1
// baseline (speedup 1.0000x reference)
#include <cuda_runtime.h>
#include <cuda_bf16.h>
#include <cstdint>

using bf16 = __nv_bfloat16;

constexpr int NN  = 8192;    // nodes
constexpr int HD  = 512;     // hidden
constexpr int EE  = NN * 8;  // edges
constexpr float TAUI = 1.25f;  // 1/tau

constexpr int BM = 128, BN = 128, BK = 32;
constexpr int LDK = BK + 8;   // padded smem leading dim (bf16 elems) -> conflict-free ldmatrix

// ---------------- device scratch (no allocation allowed) ----------------
__device__ bf16  g_zmp[NN*HD];
__device__ bf16  g_zsc[NN*HD];
__device__ bf16  g_W1b[HD*HD];
__device__ bf16  g_W2b[HD*HD];
__device__ bf16  g_H  [NN*HD];   // hidden activations (reused for both views)
__device__ float g_P  [NN*HD];   // projection output (reused for both views)
__device__ bf16  g_n1 [NN*HD];
__device__ bf16  g_n2 [NN*HD];
__device__ float g_rowsum[NN];
__device__ float g_colsum[NN];
__device__ float g_smp[NN];
__device__ float g_ssc[NN];

// ---------------- PTX helpers ----------------
__device__ __forceinline__ uint32_t sm32(const void* p){
  return (uint32_t)__cvta_generic_to_shared(p);
}
__device__ __forceinline__ void cp16(uint32_t s, const void* g){
  asm volatile("cp.async.cg.shared.global [%0], [%1], 16;\n" :: "r"(s), "l"(g));
}
__device__ __forceinline__ void cp_commit(){ asm volatile("cp.async.commit_group;\n" ::: "memory"); }
__device__ __forceinline__ void cp_wait0(){ asm volatile("cp.async.wait_group 0;\n" ::: "memory"); }

__device__ __forceinline__ void ldsm4(uint32_t r[4], uint32_t a){
  asm volatile("ldmatrix.sync.aligned.m8n8.x4.shared.b16 {%0,%1,%2,%3}, [%4];\n"
    : "=r"(r[0]), "=r"(r[1]), "=r"(r[2]), "=r"(r[3]) : "r"(a));
}
__device__ __forceinline__ void mma_bf16(float c[4], const uint32_t a[4], uint32_t b0, uint32_t b1){
  asm volatile("mma.sync.aligned.m16n8k16.row.col.f32.bf16.bf16.f32 "
    "{%0,%1,%2,%3},{%4,%5,%6,%7},{%8,%9},{%0,%1,%2,%3};\n"
    : "+f"(c[0]), "+f"(c[1]), "+f"(c[2]), "+f"(c[3])
    : "r"(a[0]), "r"(a[1]), "r"(a[2]), "r"(a[3]), "r"(b0), "r"(b1));
}

// Load 128x32 bf16 tiles of A and B (both row-major, K contiguous) into padded smem.
__device__ __forceinline__ void load_tiles(bf16* As, bf16* Bs,
    const bf16* __restrict__ A, const bf16* __restrict__ B,
    int m0, int n0, int k0, int K, int tid){
  #pragma unroll
  for(int p=0;p<2;p++){
    int ci  = tid + p*256;
    int row = ci >> 2;
    int ch  = ci & 3;
    cp16(sm32(As + row*LDK + ch*8), A + (size_t)(m0+row)*K + k0 + ch*8);
    cp16(sm32(Bs + row*LDK + ch*8), B + (size_t)(n0+row)*K + k0 + ch*8);
  }
}

// One BK=32 slab of MMAs. Warp tile 32(m) x 64(n); frags: 2(m) x 8(n).
__device__ __forceinline__ void mma_tile(float acc[2][8][4],
    const bf16* As, const bf16* Bs, int wm, int wn, int lane){
  #pragma unroll
  for(int ks=0; ks<2; ks++){
    uint32_t a[2][4], b[4][4];
    #pragma unroll
    for(int mi=0; mi<2; mi++)
      ldsm4(a[mi], sm32(As + (wm*32 + mi*16 + (lane&15))*LDK + ks*16 + (lane>>4)*8));
    #pragma unroll
    for(int nf=0; nf<4; nf++)
      ldsm4(b[nf], sm32(Bs + (wn*64 + nf*16 + (lane&15))*LDK + ks*16 + (lane>>4)*8));
    #pragma unroll
    for(int mi=0; mi<2; mi++)
      #pragma unroll
      for(int ni=0; ni<8; ni++)
        mma_bf16(acc[mi][ni], a[mi], b[ni>>1][ni&1], b[ni>>1][(ni&1)+2]);
  }
}

// ---------------- GEMM: C = A @ B^T (+bias, optional ELU) ----------------
// EPI==0: elu(acc+bias) -> bf16 outH ; EPI==1: acc+bias -> fp32 outP
template<int EPI>
__global__ void __launch_bounds__(256) gemm_nt(
    const bf16* __restrict__ A, const bf16* __restrict__ B,
    const float* __restrict__ bias, bf16* __restrict__ outH,
    float* __restrict__ outP, int M, int N, int K)
{
  __shared__ bf16 As[2][BM*LDK];
  __shared__ bf16 Bs[2][BN*LDK];
  int tid = threadIdx.x, lane = tid & 31, warp = tid >> 5;
  int wm = warp >> 1, wn = warp & 1;             // 4x2 warp grid
  int m0 = blockIdx.y * BM, n0 = blockIdx.x * BN;

  float acc[2][8][4];
  #pragma unroll
  for(int i=0;i<2;i++) for(int j=0;j<8;j++) for(int k=0;k<4;k++) acc[i][j][k]=0.f;

  int nk = K / BK;
  load_tiles(As[0], Bs[0], A, B, m0, n0, 0, K, tid);
  cp_commit();
  for(int kt=0; kt<nk; kt++){
    cp_wait0();
    __syncthreads();
    if(kt+1 < nk){
      load_tiles(As[(kt+1)&1], Bs[(kt+1)&1], A, B, m0, n0, (kt+1)*BK, K, tid);
      cp_commit();
    }
    mma_tile(acc, As[kt&1], Bs[kt&1], wm, wn, lane);
  }

  int mb = m0 + wm*32, nb = n0 + wn*64;
  #pragma unroll
  for(int mi=0; mi<2; mi++){
    #pragma unroll
    for(int ni=0; ni<8; ni++){
      int r = mb + mi*16 + (lane>>2);
      int c = nb + ni*8 + (lane&3)*2;
      float bv0 = bias[c], bv1 = bias[c+1];
      float v0 = acc[mi][ni][0] + bv0;
      float v1 = acc[mi][ni][1] + bv1;
      float v2 = acc[mi][ni][2] + bv0;
      float v3 = acc[mi][ni][3] + bv1;
      if(EPI == 0){
        v0 = v0 > 0.f ? v0 : (__expf(v0) - 1.f);
        v1 = v1 > 0.f ? v1 : (__expf(v1) - 1.f);
        v2 = v2 > 0.f ? v2 : (__expf(v2) - 1.f);
        v3 = v3 > 0.f ? v3 : (__expf(v3) - 1.f);
        *(__nv_bfloat162*)(outH + (size_t)r*N + c)     = __floats2bfloat162_rn(v0, v1);
        *(__nv_bfloat162*)(outH + (size_t)(r+8)*N + c) = __floats2bfloat162_rn(v2, v3);
      } else {
        *(float2*)(outP + (size_t)r*N + c)     = make_float2(v0, v1);
        *(float2*)(outP + (size_t)(r+8)*N + c) = make_float2(v2, v3);
      }
    }
  }
}

// ---------------- fused S-pass: rowsum/colsum of exp(n1@n2^T / tau) ----------------
__global__ void __launch_bounds__(256) sim_kernel(
    const bf16* __restrict__ A, const bf16* __restrict__ B,
    float* __restrict__ rowsum, float* __restrict__ colsum)
{
  __shared__ bf16 As[2][BM*LDK];
  __shared__ bf16 Bs[2][BN*LDK];
  int tid = threadIdx.x, lane = tid & 31, warp = tid >> 5;
  int wm = warp >> 1, wn = warp & 1;
  int m0 = blockIdx.y * BM, n0 = blockIdx.x * BN;

  float acc[2][8][4];
  #pragma unroll
  for(int i=0;i<2;i++) for(int j=0;j<8;j++) for(int k=0;k<4;k++) acc[i][j][k]=0.f;

  int nk = HD / BK;
  load_tiles(As[0], Bs[0], A, B, m0, n0, 0, HD, tid);
  cp_commit();
  for(int kt=0; kt<nk; kt++){
    cp_wait0();
    __syncthreads();
    if(kt+1 < nk){
      load_tiles(As[(kt+1)&1], Bs[(kt+1)&1], A, B, m0, n0, (kt+1)*BK, HD, tid);
      cp_commit();
    }
    mma_tile(acc, As[kt&1], Bs[kt&1], wm, wn, lane);
  }

  // fused epilogue: exp + partial row/col sums (never materialize S)
  float rp[2][2] = {{0.f,0.f},{0.f,0.f}};
  float cp[8][2];
  #pragma unroll
  for(int i=0;i<8;i++){ cp[i][0]=0.f; cp[i][1]=0.f; }
  #pragma unroll
  for(int mi=0;mi<2;mi++){
    #pragma unroll
    for(int ni=0;ni<8;ni++){
      float e0 = __expf(acc[mi][ni][0]*TAUI);
      float e1 = __expf(acc[mi][ni][1]*TAUI);
      float e2 = __expf(acc[mi][ni][2]*TAUI);
      float e3 = __expf(acc[mi][ni][3]*TAUI);
      rp[mi][0] += e0+e1; rp[mi][1] += e2+e3;
      cp[ni][0] += e0+e2; cp[ni][1] += e1+e3;
    }
  }
  int mb = m0 + wm*32, nb = n0 + wn*64;
  #pragma unroll
  for(int mi=0;mi<2;mi++){
    #pragma unroll
    for(int rr=0;rr<2;rr++){
      float v = rp[mi][rr];
      v += __shfl_xor_sync(0xffffffffu, v, 1);
      v += __shfl_xor_sync(0xffffffffu, v, 2);
      if((lane&3)==0) atomicAdd(&rowsum[mb + mi*16 + rr*8 + (lane>>2)], v);
    }
  }
  #pragma unroll
  for(int ni=0;ni<8;ni++){
    #pragma unroll
    for(int j=0;j<2;j++){
      float v = cp[ni][j];
      v += __shfl_xor_sync(0xffffffffu, v, 4);
      v += __shfl_xor_sync(0xffffffffu, v, 8);
      v += __shfl_xor_sync(0xffffffffu, v, 16);
      if(lane < 4) atomicAdd(&colsum[nb + ni*8 + lane*2 + j], v);
    }
  }
}

// ---------------- small kernels ----------------
__global__ void zero_kernel(){
  int i = blockIdx.x*blockDim.x + threadIdx.x;
  if(i < NN){ g_rowsum[i]=0.f; g_colsum[i]=0.f; g_smp[i]=0.f; g_ssc[i]=0.f; }
}

__global__ void convert_kernel(const float* __restrict__ zmp, const float* __restrict__ zsc,
                               const float* __restrict__ W1, const float* __restrict__ W2){
  int i = blockIdx.x*blockDim.x + threadIdx.x;
  if(i < NN*HD){
    g_zmp[i] = __float2bfloat16(zmp[i]);
    g_zsc[i] = __float2bfloat16(zsc[i]);
  }
  if(i < HD*HD){
    g_W1b[i] = __float2bfloat16(W1[i]);
    g_W2b[i] = __float2bfloat16(W2[i]);
  }
}

// one warp per row: L2-normalize fp32 row -> bf16
__global__ void normalize_kernel(const float* __restrict__ P, bf16* __restrict__ out){
  int warp = threadIdx.x >> 5, lane = threadIdx.x & 31;
  int row  = blockIdx.x * 8 + warp;
  const float4* pv = (const float4*)(P + (size_t)row*HD);
  float4 v[4];
  float s = 0.f;
  #pragma unroll
  for(int q=0;q<4;q++){
    v[q] = pv[lane*4+q];
    s += v[q].x*v[q].x + v[q].y*v[q].y + v[q].z*v[q].z + v[q].w*v[q].w;
  }
  #pragma unroll
  for(int off=16; off>0; off>>=1) s += __shfl_xor_sync(0xffffffffu, s, off);
  float rn = rsqrtf(s);
  uint2* ov = (uint2*)(out + (size_t)row*HD);
  #pragma unroll
  for(int q=0;q<4;q++){
    __nv_bfloat162 lo = __floats2bfloat162_rn(v[q].x*rn, v[q].y*rn);
    __nv_bfloat162 hi = __floats2bfloat162_rn(v[q].z*rn, v[q].w*rn);
    uint2 pk;
    pk.x = *(uint32_t*)&lo; pk.y = *(uint32_t*)&hi;
    ov[lane*4+q] = pk;
  }
}

__device__ __forceinline__ float dot512(const bf16* __restrict__ x,
                                        const bf16* __restrict__ y, int lane){
  const uint4* xv = (const uint4*)x;
  const uint4* yv = (const uint4*)y;
  float s = 0.f;
  #pragma unroll
  for(int q=0;q<2;q++){
    uint4 ux = xv[lane*2+q], uy = yv[lane*2+q];
    const __nv_bfloat162* px = (const __nv_bfloat162*)&ux;
    const __nv_bfloat162* py = (const __nv_bfloat162*)&uy;
    #pragma unroll
    for(int j=0;j<4;j++){
      float2 fx = __bfloat1622float2(px[j]);
      float2 fy = __bfloat1622float2(py[j]);
      s += fx.x*fy.x + fx.y*fy.y;
    }
  }
  return s;
}

// one warp per edge: v_mp = S[r,c]/rowsum[r], v_sc = S[c,r]/colsum[r]; segment-sum by row.
__global__ void edge_kernel(const void* __restrict__ posv,
                            const bf16* __restrict__ n1, const bf16* __restrict__ n2,
                            const float* __restrict__ rowsum, const float* __restrict__ colsum,
                            float* __restrict__ smp, float* __restrict__ ssc){
  int e    = (blockIdx.x*blockDim.x + threadIdx.x) >> 5;
  int lane = threadIdx.x & 31;
  if(e >= EE) return;
  const long long* p64 = (const long long*)posv;
  const int*       p32 = (const int*)posv;
  // row = repeat(arange(8192), 8): if int64, p64[32767]==4095; if int32, it packs 8191|8191<<32.
  bool is64 = (p64[32767] == 4095LL);
  int r, c;
  if(is64){ r = (int)p64[e]; c = (int)p64[EE + e]; }
  else    { r = p32[e];      c = p32[EE + e];      }

  float d1 = dot512(n1 + (size_t)r*HD, n2 + (size_t)c*HD, lane);  // S[r,c] arg
  float d2 = dot512(n1 + (size_t)c*HD, n2 + (size_t)r*HD, lane);  // S[c,r] arg
  #pragma unroll
  for(int off=16; off>0; off>>=1){
    d1 += __shfl_xor_sync(0xffffffffu, d1, off);
    d2 += __shfl_xor_sync(0xffffffffu, d2, off);
  }
  if(lane == 0){
    float v1 = __expf(d1*TAUI) / rowsum[r];
    float v2 = __expf(d2*TAUI) / colsum[r];
    atomicAdd(&smp[r], v1);
    atomicAdd(&ssc[r], v2);
  }
}

__global__ void loss_kernel(const float* __restrict__ smp, const float* __restrict__ ssc,
                            float* __restrict__ out){
  __shared__ float red[1024];
  int tid = threadIdx.x;
  float s = 0.f;
  for(int i=tid; i<NN; i+=1024)
    s += 0.5f*logf(smp[i]) + 0.5f*logf(ssc[i]);
  red[tid] = s;
  __syncthreads();
  for(int st=512; st>0; st>>=1){
    if(tid < st) red[tid] += red[tid+st];
    __syncthreads();
  }
  if(tid == 0) out[0] = -red[0] / (float)NN;
}

// ---------------- launch ----------------
extern "C" void kernel_launch(void* const* d_in, const int* in_sizes, int n_in,
                              void* d_out, int out_size){
  const float* z_mp = (const float*)d_in[0];
  const float* z_sc = (const float*)d_in[1];
  const float* W1   = (const float*)d_in[2];
  const float* b1   = (const float*)d_in[3];
  const float* W2   = (const float*)d_in[4];
  const float* b2   = (const float*)d_in[5];
  const void*  pos  = d_in[6];
  float* out = (float*)d_out;

  void *zmpb, *zscb, *w1b, *w2b, *h, *p, *n1, *n2, *rs, *cs, *smp, *ssc;
  cudaGetSymbolAddress(&zmpb, g_zmp);
  cudaGetSymbolAddress(&zscb, g_zsc);
  cudaGetSymbolAddress(&w1b,  g_W1b);
  cudaGetSymbolAddress(&w2b,  g_W2b);
  cudaGetSymbolAddress(&h,    g_H);
  cudaGetSymbolAddress(&p,    g_P);
  cudaGetSymbolAddress(&n1,   g_n1);
  cudaGetSymbolAddress(&n2,   g_n2);
  cudaGetSymbolAddress(&rs,   g_rowsum);
  cudaGetSymbolAddress(&cs,   g_colsum);
  cudaGetSymbolAddress(&smp,  g_smp);
  cudaGetSymbolAddress(&ssc,  g_ssc);

  zero_kernel<<<NN/256, 256>>>();
  convert_kernel<<<(NN*HD)/256, 256>>>(z_mp, z_sc, W1, W2);

  dim3 gmlp(HD/BN, NN/BM);   // (4, 64)
  // view 1: H = elu(zmp @ W1^T + b1); P = H @ W2^T + b2; n1 = normalize(P)
  gemm_nt<0><<<gmlp, 256>>>((const bf16*)zmpb, (const bf16*)w1b, b1, (bf16*)h, nullptr, NN, HD, HD);
  gemm_nt<1><<<gmlp, 256>>>((const bf16*)h,    (const bf16*)w2b, b2, nullptr, (float*)p, NN, HD, HD);
  normalize_kernel<<<NN/8, 256>>>((const float*)p, (bf16*)n1);
  // view 2
  gemm_nt<0><<<gmlp, 256>>>((const bf16*)zscb, (const bf16*)w1b, b1, (bf16*)h, nullptr, NN, HD, HD);
  gemm_nt<1><<<gmlp, 256>>>((const bf16*)h,    (const bf16*)w2b, b2, nullptr, (float*)p, NN, HD, HD);
  normalize_kernel<<<NN/8, 256>>>((const float*)p, (bf16*)n2);

  dim3 gsim(NN/BN, NN/BM);   // (64, 64)
  sim_kernel<<<gsim, 256>>>((const bf16*)n1, (const bf16*)n2, (float*)rs, (float*)cs);

  edge_kernel<<<EE/8, 256>>>(pos, (const bf16*)n1, (const bf16*)n2,
                             (const float*)rs, (const float*)cs, (float*)smp, (float*)ssc);

  loss_kernel<<<1, 1024>>>((const float*)smp, (const float*)ssc, out);
}